// round 5
// baseline (speedup 1.0000x reference)
#include <cuda_runtime.h>

#define BB 64
#define LL 25
#define FF 128
#define PP 10000
#define GB 2          // batches per k_final block

// ---------------- device scratch ----------------
__device__ float g_q[BB*LL*FF];
__device__ float g_k[BB*LL*FF];
__device__ float g_v[BB*LL*FF];
__device__ float g_attn[BB*LL*FF];
__device__ float g_ds[BB*LL*LL];
__device__ float g_dt[BB*LL*LL];
__device__ float g_tint[BB*LL];
// 0: ds max, 1: ds min, 2: dt max, 3: dt min,
// 4: interval_s max, 5: interval_s min, 6: tint max, 7: tint min
__device__ int g_stats[8];

__device__ __forceinline__ void redMax(float v, int slot) {
    #pragma unroll
    for (int o = 16; o; o >>= 1) v = fmaxf(v, __shfl_xor_sync(0xffffffffu, v, o));
    if ((threadIdx.x & 31) == 0) atomicMax(&g_stats[slot], __float_as_int(v));
}
__device__ __forceinline__ void redMin(float v, int slot) {
    #pragma unroll
    for (int o = 16; o; o >>= 1) v = fminf(v, __shfl_xor_sync(0xffffffffu, v, o));
    if ((threadIdx.x & 31) == 0) atomicMin(&g_stats[slot], __float_as_int(v));
}

// packed fp32x2 FMA (Blackwell FFMA2, only reachable via PTX)
__device__ __forceinline__ void ffma2(unsigned long long& d, unsigned long long a, unsigned long long b) {
    asm("fma.rn.f32x2 %0, %1, %2, %0;" : "+l"(d) : "l"(a), "l"(b));
}
__device__ __forceinline__ unsigned long long pack2(float x, float y) {
    unsigned long long r; asm("mov.b64 %0, {%1, %2};" : "=l"(r) : "f"(x), "f"(y)); return r;
}
__device__ __forceinline__ float lo2(unsigned long long v) { return __uint_as_float((unsigned)v); }
__device__ __forceinline__ float hi2(unsigned long long v) { return __uint_as_float((unsigned)(v >> 32)); }

// ---------------- kernel 0: init reduction slots -------------------------------
__global__ void k_init() {
    int t = threadIdx.x;
    if (t < 8) g_stats[t] = (t & 1) ? 0x7F800000 : 0;
}

// ---------------- kernel 1: embeddings + ds/dt + tint + QKV + dist scan --------
// 384 threads: thread t -> matrix m = t>>7 (Q/K/V), column f = t&127.
// Inputs stored TRANSPOSED in smem: inT[g][l], row stride 28 floats so one
// broadcast LDS.128 yields 4 consecutive l-values (as two f32x2 pairs).
// The dist-row max/min scan (memory-bound) is folded in to fill latency.
__global__ __launch_bounds__(384) void k_prep_qkv(
        const int* __restrict__ user, const int* __restrict__ poi,
        const int* __restrict__ tod, const int* __restrict__ dow,
        const float* __restrict__ lat, const float* __restrict__ lon,
        const float* __restrict__ ut,
        const float* __restrict__ ue, const float* __restrict__ pe,
        const float* __restrict__ te, const float* __restrict__ de,
        const float* __restrict__ Wq, const float* __restrict__ bq,
        const float* __restrict__ Wk, const float* __restrict__ bk,
        const float* __restrict__ Wv, const float* __restrict__ bv,
        const float* __restrict__ dist) {
    __shared__ __align__(16) float inT[FF*28];
    int b = blockIdx.x, tid = threadIdx.x;

    // embeddings -> transposed smem
    for (int o = tid; o < LL*FF; o += 384) {
        int l = o >> 7, f = o & 127;
        int base = b*LL + l;
        float v = ue[(size_t)user[base]*FF + f] + pe[(size_t)poi[base]*FF + f]
                + te[tod[base]*FF + f] + de[dow[base]*FF + f];
        inT[f*28 + l] = v;
    }
    // zero the 3 pad columns (l = 25..27)
    for (int o = tid; o < FF*3; o += 384) inT[(o/3)*28 + 25 + (o%3)] = 0.f;

    // pairwise haversine / delta-t + stats
    const float rad = 0.017453292519943295f;
    const float INF = __int_as_float(0x7F800000);
    float mxs = 0.f, mns = INF, mxt = 0.f, mnt = INF;
    for (int e = tid; e < LL*LL; e += 384) {
        int i = e / LL, j = e % LL;
        float la1 = lat[b*LL+i], lo1 = lon[b*LL+i];
        float la2 = lat[b*LL+j], lo2 = lon[b*LL+j];
        float a = 0.5f - 0.5f*cosf((la2-la1)*rad)
                + cosf(la1*rad)*cosf(la2*rad)*(1.0f - cosf((lo2-lo1)*rad))*0.5f;
        float ds = 12742.0f * asinf(sqrtf(a));
        float dt = fabsf(ut[b*LL+i] - ut[b*LL+j]);
        g_ds[b*LL*LL + e] = ds;
        g_dt[b*LL*LL + e] = dt;
        mxs = fmaxf(mxs, ds); mns = fminf(mns, ds);
        mxt = fmaxf(mxt, dt); mnt = fminf(mnt, dt);
    }
    float mxi = 0.f, mni = INF;
    if (tid < LL) {
        float ti = (tid == 0) ? 0.f : fabsf(ut[b*LL+tid] - ut[b*LL+tid-1]);
        g_tint[b*LL + tid] = ti;
        mxi = ti; mni = ti;
    }
    redMax(mxs, 0); redMin(mns, 1);
    redMax(mxt, 2); redMin(mnt, 3);
    redMax(mxi, 6); redMin(mni, 7);
    __syncthreads();

    // fused QKV: each thread produces out[0..24][f] for its matrix
    {
        int m = tid >> 7, f = tid & 127;
        const float* W  = (m == 0) ? Wq : (m == 1) ? Wk : Wv;
        const float* bp = (m == 0) ? bq : (m == 1) ? bk : bv;
        float bias = bp[f];
        unsigned long long acc[13];
        unsigned long long binit = pack2(bias, bias);
        #pragma unroll
        for (int j = 0; j < 13; ++j) acc[j] = binit;

        #pragma unroll 4
        for (int g = 0; g < FF; ++g) {
            float w = W[g*FF + f];                       // coalesced across warp
            unsigned long long w2 = pack2(w, w);
            const ulonglong2* row = (const ulonglong2*)(inT + g*28);  // broadcast
            #pragma unroll
            for (int j = 0; j < 6; ++j) {
                ulonglong2 a = row[j];                   // l = 4j .. 4j+3
                ffma2(acc[2*j],   a.x, w2);
                ffma2(acc[2*j+1], a.y, w2);
            }
            unsigned long long a6 = ((const unsigned long long*)(inT + g*28))[12];
            ffma2(acc[12], a6, w2);
        }
        float* dst = ((m == 0) ? g_q : (m == 1) ? g_k : g_v) + (size_t)b*LL*FF;
        #pragma unroll
        for (int j = 0; j < 12; ++j) {
            dst[(2*j)*FF + f]   = lo2(acc[j]);
            dst[(2*j+1)*FF + f] = hi2(acc[j]);
        }
        dst[24*FF + f] = lo2(acc[12]);
    }

    // dist-row scan for this batch's 25 POIs (independent memory work)
    {
        float mx = 0.f, mn = INF;
        for (int idx = tid; idx < LL*(PP/4); idx += 384) {
            int l = idx / (PP/4), c = idx % (PP/4);
            const float4* d4 = (const float4*)(dist + (size_t)poi[b*LL + l] * PP);
            float4 v = d4[c];
            mx = fmaxf(mx, fmaxf(fmaxf(v.x, v.y), fmaxf(v.z, v.w)));
            mn = fminf(mn, fminf(fminf(v.x, v.y), fminf(v.z, v.w)));
        }
        redMax(mx, 4); redMin(mn, 5);
    }
}

// ---------------- kernel 2: per-batch attention (512 thr, warp softmax) --------
__global__ __launch_bounds__(512) void k_att() {
    int b = blockIdx.x, tid = threadIdx.x;
    __shared__ float qs[LL*FF], ks[LL*FF], vs[LL*FF], aw[LL*LL];
    for (int o = tid; o < LL*(FF/4); o += 512) {
        ((float4*)qs)[o] = ((const float4*)g_q)[(size_t)b*LL*(FF/4) + o];
        ((float4*)ks)[o] = ((const float4*)g_k)[(size_t)b*LL*(FF/4) + o];
        ((float4*)vs)[o] = ((const float4*)g_v)[(size_t)b*LL*(FF/4) + o];
    }
    __syncthreads();
    float su = __int_as_float(g_stats[0]), sl = __int_as_float(g_stats[1]);
    float tu = __int_as_float(g_stats[2]), tl = __int_as_float(g_stats[3]);
    float nis = -1.0f/(su - sl), nit = -1.0f/(tu - tl);
    for (int e = tid; e < LL*LL; e += 512) {
        int i = e / LL, j = e % LL;
        const float4* q4 = (const float4*)(qs + i*FF);
        const float4* k4 = (const float4*)(ks + j*FF);
        float s = 0.f;
        #pragma unroll
        for (int f = 0; f < FF/4; ++f) {
            float4 a = q4[f], c = k4[f];
            s += a.x*c.x + a.y*c.y + a.z*c.z + a.w*c.w;
        }
        float delta = 0.5f*(__expf(g_ds[b*LL*LL + e]*nis) + __expf(g_dt[b*LL*LL + e]*nit));
        aw[e] = s + delta;
    }
    __syncthreads();
    // warp-parallel softmax: warp w handles rows w, w+16
    {
        int w = tid >> 5, lane = tid & 31;
        for (int row = w; row < LL; row += 16) {
            float v = (lane < LL) ? aw[row*LL + lane] : -1e30f;
            float m = v;
            #pragma unroll
            for (int o = 16; o; o >>= 1) m = fmaxf(m, __shfl_xor_sync(0xffffffffu, m, o));
            float e = (lane < LL) ? __expf(v - m) : 0.f;
            float s = e;
            #pragma unroll
            for (int o = 16; o; o >>= 1) s += __shfl_xor_sync(0xffffffffu, s, o);
            if (lane < LL) aw[row*LL + lane] = e / s;
        }
    }
    __syncthreads();
    for (int o = tid; o < LL*FF; o += 512) {
        int i = o >> 7, f = o & 127;
        float s = 0.f;
        #pragma unroll
        for (int j = 0; j < LL; ++j) s += aw[i*LL + j] * vs[j*FF + f];
        g_attn[b*LL*FF + o] = s;
    }
}

// ---------------- kernel 3: fused candidate scoring ----------------------------
// pre[b,p] = b_val + sum_l (0.5*w_l*exp(-dist[poi_bl,p]/Ds) + 0.5*w_l*Et_bl) * <attn_bl, poi_emb_p>
// 2 candidates per thread share each A load: LDS:FFMA2 = 1:4.
__global__ __launch_bounds__(128) void k_final(
        const float* __restrict__ poi_emb, const float* __restrict__ dist,
        const int* __restrict__ poi, const float* __restrict__ w_val,
        const float* __restrict__ b_val, float* __restrict__ out, int out_size) {
    __shared__ __align__(16) float As[GB*LL*FF];
    __shared__ float sa_s[GB*LL], se_s[GB*LL];
    __shared__ unsigned drow_s[GB*LL];
    int tid = threadIdx.x;
    int b0 = blockIdx.y * GB;

    for (int o = tid; o < GB*LL*(FF/4); o += 128)
        ((float4*)As)[o] = ((const float4*)g_attn)[(size_t)b0*LL*(FF/4) + o];
    if (tid < GB*LL) {
        int l = tid % LL, b = b0 + tid/LL;
        drow_s[tid] = (unsigned)poi[b*LL + l];
        float Dt = __int_as_float(g_stats[6]) - __int_as_float(g_stats[7]);
        float s = 0.5f * w_val[l];
        sa_s[tid] = s;
        se_s[tid] = s * __expf(-g_tint[b*LL + l] / Dt);
    }
    __syncthreads();

    int p0 = blockIdx.x*256 + tid;
    int p1 = p0 + 128;
    int pc0 = min(p0, PP-1), pc1 = min(p1, PP-1);
    const ulonglong2* W0 = (const ulonglong2*)(poi_emb + (size_t)pc0 * FF);
    const ulonglong2* W1 = (const ulonglong2*)(poi_emb + (size_t)pc1 * FF);
    float nis = -1.0f / (__int_as_float(g_stats[4]) - __int_as_float(g_stats[5]));
    float bvv = b_val[0];

    for (int bi = 0; bi < GB; ++bi) {
        const ulonglong2* A2 = (const ulonglong2*)(As + bi*LL*FF);
        unsigned long long acc0[LL], acc1[LL];
        #pragma unroll
        for (int l = 0; l < LL; ++l) { acc0[l] = 0ull; acc1[l] = 0ull; }

        #pragma unroll 2
        for (int f4 = 0; f4 < FF/4; ++f4) {
            ulonglong2 w0 = W0[f4];
            ulonglong2 w1 = W1[f4];
            #pragma unroll
            for (int l = 0; l < LL; ++l) {
                ulonglong2 a = A2[l*(FF/4) + f4];    // one broadcast LDS feeds 4 FFMA2
                ffma2(acc0[l], a.x, w0.x);
                ffma2(acc0[l], a.y, w0.y);
                ffma2(acc1[l], a.x, w1.x);
                ffma2(acc1[l], a.y, w1.y);
            }
        }

        float pre0 = bvv, pre1 = bvv;
        #pragma unroll
        for (int l = 0; l < LL; ++l) {
            const float* drow = dist + (size_t)drow_s[bi*LL + l] * PP;
            float d0 = drow[pc0];
            float d1 = drow[pc1];
            float sa = sa_s[bi*LL + l], se = se_s[bi*LL + l];
            pre0 += (sa * __expf(d0*nis) + se) * (lo2(acc0[l]) + hi2(acc0[l]));
            pre1 += (sa * __expf(d1*nis) + se) * (lo2(acc1[l]) + hi2(acc1[l]));
        }
        int bcur = b0 + bi;
        bool dup = (out_size >= 2*BB*PP);
        if (p0 < PP) {
            int n = bcur*PP + p0;
            out[n] = pre0;
            if (dup) out[BB*PP + n] = pre0;
        }
        if (p1 < PP) {
            int n = bcur*PP + p1;
            out[n] = pre1;
            if (dup) out[BB*PP + n] = pre1;
        }
    }
}

// ---------------- launch ------------------------------------------------------
extern "C" void kernel_launch(void* const* d_in, const int* in_sizes, int n_in,
                              void* d_out, int out_size) {
    const int*   user  = (const int*)d_in[0];
    const int*   poi   = (const int*)d_in[1];
    // d_in[2] = cat (unused)
    const float* lat   = (const float*)d_in[3];
    const float* lon   = (const float*)d_in[4];
    const int*   tod   = (const int*)d_in[5];
    const int*   dow   = (const int*)d_in[6];
    const float* ut    = (const float*)d_in[7];
    const float* ue    = (const float*)d_in[8];
    const float* pe    = (const float*)d_in[9];
    const float* te    = (const float*)d_in[10];
    const float* de    = (const float*)d_in[11];
    const float* Wq    = (const float*)d_in[12];
    const float* bq    = (const float*)d_in[13];
    const float* Wk    = (const float*)d_in[14];
    const float* bk    = (const float*)d_in[15];
    const float* Wv    = (const float*)d_in[16];
    const float* bv    = (const float*)d_in[17];
    const float* w_val = (const float*)d_in[18];
    const float* b_val = (const float*)d_in[19];
    const float* dist  = (const float*)d_in[20];
    float* out = (float*)d_out;

    k_init<<<1, 32>>>();
    k_prep_qkv<<<BB, 384>>>(user, poi, tod, dow, lat, lon, ut, ue, pe, te, de,
                            Wq, bq, Wk, bk, Wv, bv, dist);
    k_att<<<BB, 512>>>();
    k_final<<<dim3((PP + 255)/256, BB/GB), 128>>>(pe, dist, poi, w_val, b_val, out, out_size);
}

// round 6
// speedup vs baseline: 1.5710x; 1.5710x over previous
#include <cuda_runtime.h>

#define BB 64
#define LL 25
#define FF 128
#define PP 10000
#define GB 2          // batches per k_final block
#define PT 128        // p-tile per block (1 per thread)
#define KC 16         // f per W chunk
#define NCH (FF/KC)   // 8 chunks
#define WROW 20       // padded row stride (words) for W chunk

// ---------------- device scratch ----------------
__device__ float g_q[BB*LL*FF];
__device__ float g_k[BB*LL*FF];
__device__ float g_v[BB*LL*FF];
__device__ float g_attn[BB*LL*FF];
__device__ float g_ds[BB*LL*LL];
__device__ float g_dt[BB*LL*LL];
__device__ float g_tint[BB*LL];
// 0: ds max, 1: ds min, 2: dt max, 3: dt min,
// 4: interval_s max, 5: interval_s min, 6: tint max, 7: tint min
__device__ int g_stats[8];

__device__ __forceinline__ void redMax(float v, int slot) {
    #pragma unroll
    for (int o = 16; o; o >>= 1) v = fmaxf(v, __shfl_xor_sync(0xffffffffu, v, o));
    if ((threadIdx.x & 31) == 0) atomicMax(&g_stats[slot], __float_as_int(v));
}
__device__ __forceinline__ void redMin(float v, int slot) {
    #pragma unroll
    for (int o = 16; o; o >>= 1) v = fminf(v, __shfl_xor_sync(0xffffffffu, v, o));
    if ((threadIdx.x & 31) == 0) atomicMin(&g_stats[slot], __float_as_int(v));
}

// packed fp32x2 FMA (Blackwell FFMA2, only reachable via PTX)
__device__ __forceinline__ void ffma2(unsigned long long& d, unsigned long long a, unsigned long long b) {
    asm("fma.rn.f32x2 %0, %1, %2, %0;" : "+l"(d) : "l"(a), "l"(b));
}
__device__ __forceinline__ unsigned long long pack2(float x, float y) {
    unsigned long long r; asm("mov.b64 %0, {%1, %2};" : "=l"(r) : "f"(x), "f"(y)); return r;
}
__device__ __forceinline__ float lo2(unsigned long long v) { return __uint_as_float((unsigned)v); }
__device__ __forceinline__ float hi2(unsigned long long v) { return __uint_as_float((unsigned)(v >> 32)); }

// async 16B copy global -> shared (LDGSTS)
__device__ __forceinline__ void cp16(unsigned dst_smem, const void* src) {
    asm volatile("cp.async.cg.shared.global [%0], [%1], 16;\n" :: "r"(dst_smem), "l"(src));
}
__device__ __forceinline__ void cp_commit() {
    asm volatile("cp.async.commit_group;\n");
}
template<int N> __device__ __forceinline__ void cp_wait() {
    asm volatile("cp.async.wait_group %0;\n" :: "n"(N));
}

// ---------------- kernel 0: init reduction slots -------------------------------
__global__ void k_init() {
    int t = threadIdx.x;
    if (t < 8) g_stats[t] = (t & 1) ? 0x7F800000 : 0;
}

// ---------------- kernel 1: embeddings + ds/dt + tint + QKV + dist scan --------
__global__ __launch_bounds__(384) void k_prep_qkv(
        const int* __restrict__ user, const int* __restrict__ poi,
        const int* __restrict__ tod, const int* __restrict__ dow,
        const float* __restrict__ lat, const float* __restrict__ lon,
        const float* __restrict__ ut,
        const float* __restrict__ ue, const float* __restrict__ pe,
        const float* __restrict__ te, const float* __restrict__ de,
        const float* __restrict__ Wq, const float* __restrict__ bq,
        const float* __restrict__ Wk, const float* __restrict__ bk,
        const float* __restrict__ Wv, const float* __restrict__ bv,
        const float* __restrict__ dist) {
    __shared__ __align__(16) float inT[FF*28];
    int b = blockIdx.x, tid = threadIdx.x;

    for (int o = tid; o < LL*FF; o += 384) {
        int l = o >> 7, f = o & 127;
        int base = b*LL + l;
        float v = ue[(size_t)user[base]*FF + f] + pe[(size_t)poi[base]*FF + f]
                + te[tod[base]*FF + f] + de[dow[base]*FF + f];
        inT[f*28 + l] = v;
    }
    for (int o = tid; o < FF*3; o += 384) inT[(o/3)*28 + 25 + (o%3)] = 0.f;

    const float rad = 0.017453292519943295f;
    const float INF = __int_as_float(0x7F800000);
    float mxs = 0.f, mns = INF, mxt = 0.f, mnt = INF;
    for (int e = tid; e < LL*LL; e += 384) {
        int i = e / LL, j = e % LL;
        float la1 = lat[b*LL+i], lo1 = lon[b*LL+i];
        float la2 = lat[b*LL+j], lo2 = lon[b*LL+j];
        float a = 0.5f - 0.5f*cosf((la2-la1)*rad)
                + cosf(la1*rad)*cosf(la2*rad)*(1.0f - cosf((lo2-lo1)*rad))*0.5f;
        float ds = 12742.0f * asinf(sqrtf(a));
        float dt = fabsf(ut[b*LL+i] - ut[b*LL+j]);
        g_ds[b*LL*LL + e] = ds;
        g_dt[b*LL*LL + e] = dt;
        mxs = fmaxf(mxs, ds); mns = fminf(mns, ds);
        mxt = fmaxf(mxt, dt); mnt = fminf(mnt, dt);
    }
    float mxi = 0.f, mni = INF;
    if (tid < LL) {
        float ti = (tid == 0) ? 0.f : fabsf(ut[b*LL+tid] - ut[b*LL+tid-1]);
        g_tint[b*LL + tid] = ti;
        mxi = ti; mni = ti;
    }
    redMax(mxs, 0); redMin(mns, 1);
    redMax(mxt, 2); redMin(mnt, 3);
    redMax(mxi, 6); redMin(mni, 7);
    __syncthreads();

    {
        int m = tid >> 7, f = tid & 127;
        const float* W  = (m == 0) ? Wq : (m == 1) ? Wk : Wv;
        const float* bp = (m == 0) ? bq : (m == 1) ? bk : bv;
        float bias = bp[f];
        unsigned long long acc[13];
        unsigned long long binit = pack2(bias, bias);
        #pragma unroll
        for (int j = 0; j < 13; ++j) acc[j] = binit;

        #pragma unroll 4
        for (int g = 0; g < FF; ++g) {
            float w = W[g*FF + f];
            unsigned long long w2 = pack2(w, w);
            const ulonglong2* row = (const ulonglong2*)(inT + g*28);
            #pragma unroll
            for (int j = 0; j < 6; ++j) {
                ulonglong2 a = row[j];
                ffma2(acc[2*j],   a.x, w2);
                ffma2(acc[2*j+1], a.y, w2);
            }
            unsigned long long a6 = ((const unsigned long long*)(inT + g*28))[12];
            ffma2(acc[12], a6, w2);
        }
        float* dst = ((m == 0) ? g_q : (m == 1) ? g_k : g_v) + (size_t)b*LL*FF;
        #pragma unroll
        for (int j = 0; j < 12; ++j) {
            dst[(2*j)*FF + f]   = lo2(acc[j]);
            dst[(2*j+1)*FF + f] = hi2(acc[j]);
        }
        dst[24*FF + f] = lo2(acc[12]);
    }

    {
        float mx = 0.f, mn = INF;
        for (int idx = tid; idx < LL*(PP/4); idx += 384) {
            int l = idx / (PP/4), c = idx % (PP/4);
            const float4* d4 = (const float4*)(dist + (size_t)poi[b*LL + l] * PP);
            float4 v = d4[c];
            mx = fmaxf(mx, fmaxf(fmaxf(v.x, v.y), fmaxf(v.z, v.w)));
            mn = fminf(mn, fminf(fminf(v.x, v.y), fminf(v.z, v.w)));
        }
        redMax(mx, 4); redMin(mn, 5);
    }
}

// ---------------- kernel 2: per-batch attention (512 thr, warp softmax) --------
__global__ __launch_bounds__(512) void k_att() {
    int b = blockIdx.x, tid = threadIdx.x;
    __shared__ float qs[LL*FF], ks[LL*FF], vs[LL*FF], aw[LL*LL];
    for (int o = tid; o < LL*(FF/4); o += 512) {
        ((float4*)qs)[o] = ((const float4*)g_q)[(size_t)b*LL*(FF/4) + o];
        ((float4*)ks)[o] = ((const float4*)g_k)[(size_t)b*LL*(FF/4) + o];
        ((float4*)vs)[o] = ((const float4*)g_v)[(size_t)b*LL*(FF/4) + o];
    }
    __syncthreads();
    float su = __int_as_float(g_stats[0]), sl = __int_as_float(g_stats[1]);
    float tu = __int_as_float(g_stats[2]), tl = __int_as_float(g_stats[3]);
    float nis = -1.0f/(su - sl), nit = -1.0f/(tu - tl);
    for (int e = tid; e < LL*LL; e += 512) {
        int i = e / LL, j = e % LL;
        const float4* q4 = (const float4*)(qs + i*FF);
        const float4* k4 = (const float4*)(ks + j*FF);
        float s = 0.f;
        #pragma unroll
        for (int f = 0; f < FF/4; ++f) {
            float4 a = q4[f], c = k4[f];
            s += a.x*c.x + a.y*c.y + a.z*c.z + a.w*c.w;
        }
        float delta = 0.5f*(__expf(g_ds[b*LL*LL + e]*nis) + __expf(g_dt[b*LL*LL + e]*nit));
        aw[e] = s + delta;
    }
    __syncthreads();
    {
        int w = tid >> 5, lane = tid & 31;
        for (int row = w; row < LL; row += 16) {
            float v = (lane < LL) ? aw[row*LL + lane] : -1e30f;
            float m = v;
            #pragma unroll
            for (int o = 16; o; o >>= 1) m = fmaxf(m, __shfl_xor_sync(0xffffffffu, m, o));
            float e = (lane < LL) ? __expf(v - m) : 0.f;
            float s = e;
            #pragma unroll
            for (int o = 16; o; o >>= 1) s += __shfl_xor_sync(0xffffffffu, s, o);
            if (lane < LL) aw[row*LL + lane] = e / s;
        }
    }
    __syncthreads();
    for (int o = tid; o < LL*FF; o += 512) {
        int i = o >> 7, f = o & 127;
        float s = 0.f;
        #pragma unroll
        for (int j = 0; j < LL; ++j) s += aw[i*LL + j] * vs[j*FF + f];
        g_attn[b*LL*FF + o] = s;
    }
}

// ---------------- kernel 3: fused candidate scoring (smem-W, cp.async) ---------
// pre[b,p] = b_val + sum_l (0.5*w_l*exp(-dist[poi_bl,p]/Ds) + 0.5*w_l*Et_bl) * <attn_bl, poi_emb_p>
__global__ __launch_bounds__(PT, 3) void k_final(
        const float* __restrict__ poi_emb, const float* __restrict__ dist,
        const int* __restrict__ poi, const float* __restrict__ w_val,
        const float* __restrict__ b_val, float* __restrict__ out, int out_size) {
    __shared__ __align__(16) float As[GB*LL*FF];          // 25.6 KB
    __shared__ __align__(16) float Wc[2*PT*WROW];         // 20.5 KB (2 bufs)
    __shared__ float sa_s[GB*LL], se_s[GB*LL];
    __shared__ unsigned drow_s[GB*LL];

    int tid = threadIdx.x;
    int b0 = blockIdx.y * GB;
    int p0 = blockIdx.x * PT;

    // stage attn for GB batches
    for (int o = tid; o < GB*LL*(FF/4); o += PT)
        ((float4*)As)[o] = ((const float4*)g_attn)[(size_t)b0*LL*(FF/4) + o];
    if (tid < GB*LL) {
        int l = tid % LL, b = b0 + tid/LL;
        drow_s[tid] = (unsigned)poi[b*LL + l];
        float Dt = __int_as_float(g_stats[6]) - __int_as_float(g_stats[7]);
        float s = 0.5f * w_val[l];
        sa_s[tid] = s;
        se_s[tid] = s * __expf(-g_tint[b*LL + l] / Dt);
    }

    unsigned wc_base = (unsigned)__cvta_generic_to_shared(Wc);
    // issue chunk ch into buffer buf: PT rows x KC floats, 4x 16B segs per row
    auto issue = [&](int ch, int buf) {
        #pragma unroll
        for (int k = 0; k < 4; ++k) {
            int s = k*PT + tid;
            int row = s >> 2, seg = s & 3;              // row 0..127, seg 0..3
            int prow = min(p0 + row, PP-1);
            const float* src = poi_emb + (size_t)prow*FF + ch*KC + seg*4;
            unsigned dst = wc_base + ((buf*PT + row)*WROW + seg*4)*4;
            cp16(dst, src);
        }
        cp_commit();
    };

    issue(0, 0);

    unsigned long long acc[GB][LL];
    #pragma unroll
    for (int bi = 0; bi < GB; ++bi)
        #pragma unroll
        for (int l = 0; l < LL; ++l) acc[bi][l] = 0ull;

    const char* As_b = (const char*)As;

    for (int ch = 0; ch < NCH; ++ch) {
        int buf = ch & 1;
        if (ch + 1 < NCH) issue(ch + 1, (ch + 1) & 1);
        if (ch + 1 < NCH) cp_wait<1>(); else cp_wait<0>();
        __syncthreads();                                 // buf[ch] visible to all

        const ulonglong2* wrow = (const ulonglong2*)(Wc + (buf*PT + tid)*WROW);
        #pragma unroll
        for (int j = 0; j < KC/4; ++j) {
            ulonglong2 w = wrow[j];                      // own p row, smem
            int fb = (ch*(KC/4) + j) * 16;               // byte offset along f
            #pragma unroll
            for (int bi = 0; bi < GB; ++bi) {
                #pragma unroll
                for (int l = 0; l < LL; ++l) {
                    ulonglong2 a = *(const ulonglong2*)(As_b + (bi*LL + l)*512 + fb);
                    ffma2(acc[bi][l], a.x, w.x);
                    ffma2(acc[bi][l], a.y, w.y);
                }
            }
        }
        __syncthreads();                                 // done reading buf before reuse
    }

    // epilogue
    int p = p0 + tid;
    int pc = min(p, PP-1);
    float nis = -1.0f / (__int_as_float(g_stats[4]) - __int_as_float(g_stats[5]));
    float bvv = b_val[0];
    bool dup = (out_size >= 2*BB*PP);

    #pragma unroll
    for (int bi = 0; bi < GB; ++bi) {
        float dv[LL];
        #pragma unroll
        for (int l = 0; l < LL; ++l) dv[l] = dist[(size_t)drow_s[bi*LL + l]*PP + pc];
        float pre = bvv;
        #pragma unroll
        for (int l = 0; l < LL; ++l) {
            float g = lo2(acc[bi][l]) + hi2(acc[bi][l]);
            pre += (sa_s[bi*LL + l] * __expf(dv[l]*nis) + se_s[bi*LL + l]) * g;
        }
        if (p < PP) {
            int n = (b0 + bi)*PP + p;
            out[n] = pre;
            if (dup) out[BB*PP + n] = pre;
        }
    }
}

// ---------------- launch ------------------------------------------------------
extern "C" void kernel_launch(void* const* d_in, const int* in_sizes, int n_in,
                              void* d_out, int out_size) {
    const int*   user  = (const int*)d_in[0];
    const int*   poi   = (const int*)d_in[1];
    // d_in[2] = cat (unused)
    const float* lat   = (const float*)d_in[3];
    const float* lon   = (const float*)d_in[4];
    const int*   tod   = (const int*)d_in[5];
    const int*   dow   = (const int*)d_in[6];
    const float* ut    = (const float*)d_in[7];
    const float* ue    = (const float*)d_in[8];
    const float* pe    = (const float*)d_in[9];
    const float* te    = (const float*)d_in[10];
    const float* de    = (const float*)d_in[11];
    const float* Wq    = (const float*)d_in[12];
    const float* bq    = (const float*)d_in[13];
    const float* Wk    = (const float*)d_in[14];
    const float* bk    = (const float*)d_in[15];
    const float* Wv    = (const float*)d_in[16];
    const float* bv    = (const float*)d_in[17];
    const float* w_val = (const float*)d_in[18];
    const float* b_val = (const float*)d_in[19];
    const float* dist  = (const float*)d_in[20];
    float* out = (float*)d_out;

    k_init<<<1, 32>>>();
    k_prep_qkv<<<BB, 384>>>(user, poi, tod, dow, lat, lon, ut, ue, pe, te, de,
                            Wq, bq, Wk, bk, Wv, bv, dist);
    k_att<<<BB, 512>>>();
    k_final<<<dim3((PP + PT - 1)/PT, BB/GB), PT>>>(pe, dist, poi, w_val, b_val, out, out_size);
}

// round 8
// speedup vs baseline: 2.1460x; 1.3660x over previous
#include <cuda_runtime.h>
#include <cstdint>

#define BB 64
#define LL 25
#define FF 128
#define PP 10000
#define PT 256        // p-tile per block (2 per thread)
#define NT 128        // threads per k_final block
#define KC 16         // f per W chunk
#define NCH (FF/KC)   // 8 chunks
#define WROW 20       // padded row stride (words) for W chunk
#define WC_BYTES (2*PT*WROW*4)   // 40960

// ---------------- device scratch ----------------
__device__ float g_q[BB*LL*FF];
__device__ float g_k[BB*LL*FF];
__device__ float g_v[BB*LL*FF];
__device__ float g_attn[BB*LL*FF];
__device__ float g_ds[BB*LL*LL];
__device__ float g_dt[BB*LL*LL];
__device__ float g_tint[BB*LL];
// 0:ds max 1:ds min 2:dt max 3:dt min 4:is max 5:is min 6:ti max 7:ti min
__device__ int g_stats[8];

__device__ __forceinline__ void redMax(float v, int slot) {
    #pragma unroll
    for (int o = 16; o; o >>= 1) v = fmaxf(v, __shfl_xor_sync(0xffffffffu, v, o));
    if ((threadIdx.x & 31) == 0) atomicMax(&g_stats[slot], __float_as_int(v));
}
__device__ __forceinline__ void redMin(float v, int slot) {
    #pragma unroll
    for (int o = 16; o; o >>= 1) v = fminf(v, __shfl_xor_sync(0xffffffffu, v, o));
    if ((threadIdx.x & 31) == 0) atomicMin(&g_stats[slot], __float_as_int(v));
}

// packed fp32x2 FMA (Blackwell FFMA2, only reachable via PTX)
__device__ __forceinline__ void ffma2(unsigned long long& d, unsigned long long a, unsigned long long b) {
    asm("fma.rn.f32x2 %0, %1, %2, %0;" : "+l"(d) : "l"(a), "l"(b));
}
__device__ __forceinline__ unsigned long long pack2(float x, float y) {
    unsigned long long r; asm("mov.b64 %0, {%1, %2};" : "=l"(r) : "f"(x), "f"(y)); return r;
}
__device__ __forceinline__ float lo2(unsigned long long v) { return __uint_as_float((unsigned)v); }
__device__ __forceinline__ float hi2(unsigned long long v) { return __uint_as_float((unsigned)(v >> 32)); }

// async 16B copy global -> shared (LDGSTS)
__device__ __forceinline__ void cp16(unsigned dst_smem, const void* src) {
    asm volatile("cp.async.cg.shared.global [%0], [%1], 16;\n" :: "r"(dst_smem), "l"(src));
}
__device__ __forceinline__ void cp_commit() {
    asm volatile("cp.async.commit_group;\n");
}
template<int N> __device__ __forceinline__ void cp_wait() {
    asm volatile("cp.async.wait_group %0;\n" :: "n"(N));
}

// ---------------- kernel 0: init reduction slots -------------------------------
__global__ void k_init() {
    int t = threadIdx.x;
    if (t < 8) g_stats[t] = (t & 1) ? 0x7F800000 : 0;
}

// ---------------- kernel 1: embeddings + ds/dt + tint + QKV | dist scan --------
// gridDim.y == 2: y=0 blocks do embeddings/haversine/QKV, y=1 blocks scan dist.
__global__ __launch_bounds__(384) void k_prep_qkv(
        const int* __restrict__ user, const int* __restrict__ poi,
        const int* __restrict__ tod, const int* __restrict__ dow,
        const float* __restrict__ lat, const float* __restrict__ lon,
        const float* __restrict__ ut,
        const float* __restrict__ ue, const float* __restrict__ pe,
        const float* __restrict__ te, const float* __restrict__ de,
        const float* __restrict__ Wq, const float* __restrict__ bq,
        const float* __restrict__ Wk, const float* __restrict__ bk,
        const float* __restrict__ Wv, const float* __restrict__ bv,
        const float* __restrict__ dist) {
    int b = blockIdx.x, tid = threadIdx.x;
    const float INF = __int_as_float(0x7F800000);

    if (blockIdx.y == 1) {
        // dist-row max/min scan for this batch's 25 POIs
        float mx = 0.f, mn = INF;
        for (int idx = tid; idx < LL*(PP/4); idx += 384) {
            int l = idx / (PP/4), c = idx % (PP/4);
            const float4* d4 = (const float4*)(dist + (size_t)poi[b*LL + l] * PP);
            float4 v = d4[c];
            mx = fmaxf(mx, fmaxf(fmaxf(v.x, v.y), fmaxf(v.z, v.w)));
            mn = fminf(mn, fminf(fminf(v.x, v.y), fminf(v.z, v.w)));
        }
        redMax(mx, 4); redMin(mn, 5);
        return;
    }

    __shared__ __align__(16) float inT[FF*28];

    for (int o = tid; o < LL*FF; o += 384) {
        int l = o >> 7, f = o & 127;
        int base = b*LL + l;
        float v = ue[(size_t)user[base]*FF + f] + pe[(size_t)poi[base]*FF + f]
                + te[tod[base]*FF + f] + de[dow[base]*FF + f];
        inT[f*28 + l] = v;
    }
    for (int o = tid; o < FF*3; o += 384) inT[(o/3)*28 + 25 + (o%3)] = 0.f;

    const float rad = 0.017453292519943295f;
    float mxs = 0.f, mns = INF, mxt = 0.f, mnt = INF;
    for (int e = tid; e < LL*LL; e += 384) {
        int i = e / LL, j = e % LL;
        float la1 = lat[b*LL+i], lo1 = lon[b*LL+i];
        float la2 = lat[b*LL+j], lo2 = lon[b*LL+j];
        float a = 0.5f - 0.5f*cosf((la2-la1)*rad)
                + cosf(la1*rad)*cosf(la2*rad)*(1.0f - cosf((lo2-lo1)*rad))*0.5f;
        float ds = 12742.0f * asinf(sqrtf(a));
        float dt = fabsf(ut[b*LL+i] - ut[b*LL+j]);
        g_ds[b*LL*LL + e] = ds;
        g_dt[b*LL*LL + e] = dt;
        mxs = fmaxf(mxs, ds); mns = fminf(mns, ds);
        mxt = fmaxf(mxt, dt); mnt = fminf(mnt, dt);
    }
    float mxi = 0.f, mni = INF;
    if (tid < LL) {
        float ti = (tid == 0) ? 0.f : fabsf(ut[b*LL+tid] - ut[b*LL+tid-1]);
        g_tint[b*LL + tid] = ti;
        mxi = ti; mni = ti;
    }
    redMax(mxs, 0); redMin(mns, 1);
    redMax(mxt, 2); redMin(mnt, 3);
    redMax(mxi, 6); redMin(mni, 7);
    __syncthreads();

    {
        int m = tid >> 7, f = tid & 127;
        const float* W  = (m == 0) ? Wq : (m == 1) ? Wk : Wv;
        const float* bp = (m == 0) ? bq : (m == 1) ? bk : bv;
        float bias = bp[f];
        unsigned long long acc[13];
        unsigned long long binit = pack2(bias, bias);
        #pragma unroll
        for (int j = 0; j < 13; ++j) acc[j] = binit;

        #pragma unroll 4
        for (int g = 0; g < FF; ++g) {
            float w = W[g*FF + f];
            unsigned long long w2 = pack2(w, w);
            const ulonglong2* row = (const ulonglong2*)(inT + g*28);
            #pragma unroll
            for (int j = 0; j < 6; ++j) {
                ulonglong2 a = row[j];
                ffma2(acc[2*j],   a.x, w2);
                ffma2(acc[2*j+1], a.y, w2);
            }
            unsigned long long a6 = ((const unsigned long long*)(inT + g*28))[12];
            ffma2(acc[12], a6, w2);
        }
        float* dst = ((m == 0) ? g_q : (m == 1) ? g_k : g_v) + (size_t)b*LL*FF;
        #pragma unroll
        for (int j = 0; j < 12; ++j) {
            dst[(2*j)*FF + f]   = lo2(acc[j]);
            dst[(2*j+1)*FF + f] = hi2(acc[j]);
        }
        dst[24*FF + f] = lo2(acc[12]);
    }
}

// ---------------- kernel 2: per-batch attention --------------------------------
__global__ __launch_bounds__(512) void k_att() {
    int b = blockIdx.x, tid = threadIdx.x;
    __shared__ float qs[LL*FF], ks[LL*FF], vs[LL*FF], aw[LL*LL];
    for (int o = tid; o < LL*(FF/4); o += 512) {
        ((float4*)qs)[o] = ((const float4*)g_q)[(size_t)b*LL*(FF/4) + o];
        ((float4*)ks)[o] = ((const float4*)g_k)[(size_t)b*LL*(FF/4) + o];
        ((float4*)vs)[o] = ((const float4*)g_v)[(size_t)b*LL*(FF/4) + o];
    }
    __syncthreads();
    float su = __int_as_float(g_stats[0]), sl = __int_as_float(g_stats[1]);
    float tu = __int_as_float(g_stats[2]), tl = __int_as_float(g_stats[3]);
    float nis = -1.0f/(su - sl), nit = -1.0f/(tu - tl);
    for (int e = tid; e < LL*LL; e += 512) {
        int i = e / LL, j = e % LL;
        const float4* q4 = (const float4*)(qs + i*FF);
        const float4* k4 = (const float4*)(ks + j*FF);
        float s = 0.f;
        #pragma unroll
        for (int f = 0; f < FF/4; ++f) {
            float4 a = q4[f], c = k4[f];
            s += a.x*c.x + a.y*c.y + a.z*c.z + a.w*c.w;
        }
        float delta = 0.5f*(__expf(g_ds[b*LL*LL + e]*nis) + __expf(g_dt[b*LL*LL + e]*nit));
        aw[e] = s + delta;
    }
    __syncthreads();
    {
        int w = tid >> 5, lane = tid & 31;
        for (int row = w; row < LL; row += 16) {
            float v = (lane < LL) ? aw[row*LL + lane] : -1e30f;
            float m = v;
            #pragma unroll
            for (int o = 16; o; o >>= 1) m = fmaxf(m, __shfl_xor_sync(0xffffffffu, m, o));
            float e = (lane < LL) ? __expf(v - m) : 0.f;
            float s = e;
            #pragma unroll
            for (int o = 16; o; o >>= 1) s += __shfl_xor_sync(0xffffffffu, s, o);
            if (lane < LL) aw[row*LL + lane] = e / s;
        }
    }
    __syncthreads();
    for (int o = tid; o < LL*FF; o += 512) {
        int i = o >> 7, f = o & 127;
        float s = 0.f;
        #pragma unroll
        for (int j = 0; j < LL; ++j) s += aw[i*LL + j] * vs[j*FF + f];
        g_attn[b*LL*FF + o] = s;
    }
}

// ---------------- kernel 3: fused candidate scoring (TP=2, smem-W cp.async) ----
// pre[b,p] = b_val + sum_l (0.5*w_l*exp(-dist[poi_bl,p]/Ds) + 0.5*w_l*Et_bl) * <attn_bl, poi_emb_p>
// Each thread owns 2 p-rows; each broadcast A-load feeds 4 FFMA2.
__global__ __launch_bounds__(NT, 3) void k_final(
        const float* __restrict__ poi_emb, const float* __restrict__ dist,
        const int* __restrict__ poi, const float* __restrict__ w_val,
        const float* __restrict__ b_val, float* __restrict__ out, int out_size) {
    extern __shared__ __align__(16) float Wc[];           // 2 bufs x PT x WROW
    __shared__ __align__(16) float As[LL*FF];             // 12.8 KB
    __shared__ float sa_s[LL], se_s[LL];
    __shared__ unsigned drow_s[LL];

    int tid = threadIdx.x;
    int b = blockIdx.y;
    int p0 = blockIdx.x * PT;

    for (int o = tid; o < LL*(FF/4); o += NT)
        ((float4*)As)[o] = ((const float4*)g_attn)[(size_t)b*LL*(FF/4) + o];
    if (tid < LL) {
        drow_s[tid] = (unsigned)poi[b*LL + tid];
        float Dt = __int_as_float(g_stats[6]) - __int_as_float(g_stats[7]);
        float s = 0.5f * w_val[tid];
        sa_s[tid] = s;
        se_s[tid] = s * __expf(-g_tint[b*LL + tid] / Dt);
    }

    unsigned wc_base = (unsigned)__cvta_generic_to_shared(Wc);
    // stage chunk ch into buffer buf: PT rows x KC floats, 4x 16B segs per row
    auto issue = [&](int ch, int buf) {
        #pragma unroll
        for (int k = 0; k < 8; ++k) {
            int s = k*NT + tid;                          // 0..1023
            int row = s >> 2, seg = s & 3;               // row 0..255
            int prow = min(p0 + row, PP-1);
            const float* src = poi_emb + (size_t)prow*FF + ch*KC + seg*4;
            unsigned dst = wc_base + ((buf*PT + row)*WROW + seg*4)*4;
            cp16(dst, src);
        }
        cp_commit();
    };

    issue(0, 0);

    unsigned long long acc0[LL], acc1[LL];
    #pragma unroll
    for (int l = 0; l < LL; ++l) { acc0[l] = 0ull; acc1[l] = 0ull; }

    const char* As_b = (const char*)As;

    for (int ch = 0; ch < NCH; ++ch) {
        int buf = ch & 1;
        if (ch + 1 < NCH) issue(ch + 1, (ch + 1) & 1);
        if (ch + 1 < NCH) cp_wait<1>(); else cp_wait<0>();
        __syncthreads();

        const ulonglong2* w0 = (const ulonglong2*)(Wc + (buf*PT + tid)*WROW);
        const ulonglong2* w1 = (const ulonglong2*)(Wc + (buf*PT + tid + NT)*WROW);
        #pragma unroll
        for (int j = 0; j < KC/4; ++j) {
            ulonglong2 wa = w0[j];
            ulonglong2 wb = w1[j];
            int fb = (ch*(KC/4) + j) * 16;
            #pragma unroll
            for (int l = 0; l < LL; ++l) {
                ulonglong2 a = *(const ulonglong2*)(As_b + l*512 + fb);
                ffma2(acc0[l], a.x, wa.x);
                ffma2(acc0[l], a.y, wa.y);
                ffma2(acc1[l], a.x, wb.x);
                ffma2(acc1[l], a.y, wb.y);
            }
        }
        __syncthreads();
    }

    // epilogue
    int pA = p0 + tid, pB = p0 + tid + NT;
    int pcA = min(pA, PP-1), pcB = min(pB, PP-1);
    float nis = -1.0f / (__int_as_float(g_stats[4]) - __int_as_float(g_stats[5]));
    float bvv = b_val[0];
    bool dup = (out_size >= 2*BB*PP);

    float preA = bvv, preB = bvv;
    #pragma unroll
    for (int l = 0; l < LL; ++l) {
        const float* drow = dist + (size_t)drow_s[l]*PP;
        float dA = drow[pcA];
        float dB = drow[pcB];
        float sa = sa_s[l], se = se_s[l];
        preA += (sa * __expf(dA*nis) + se) * (lo2(acc0[l]) + hi2(acc0[l]));
        preB += (sa * __expf(dB*nis) + se) * (lo2(acc1[l]) + hi2(acc1[l]));
    }
    if (pA < PP) {
        int n = b*PP + pA;
        out[n] = preA;
        if (dup) out[BB*PP + n] = preA;
    }
    if (pB < PP) {
        int n = b*PP + pB;
        out[n] = preB;
        if (dup) out[BB*PP + n] = preB;
    }
}

// ---------------- launch ------------------------------------------------------
extern "C" void kernel_launch(void* const* d_in, const int* in_sizes, int n_in,
                              void* d_out, int out_size) {
    const int*   user  = (const int*)d_in[0];
    const int*   poi   = (const int*)d_in[1];
    // d_in[2] = cat (unused)
    const float* lat   = (const float*)d_in[3];
    const float* lon   = (const float*)d_in[4];
    const int*   tod   = (const int*)d_in[5];
    const int*   dow   = (const int*)d_in[6];
    const float* ut    = (const float*)d_in[7];
    const float* ue    = (const float*)d_in[8];
    const float* pe    = (const float*)d_in[9];
    const float* te    = (const float*)d_in[10];
    const float* de    = (const float*)d_in[11];
    const float* Wq    = (const float*)d_in[12];
    const float* bq    = (const float*)d_in[13];
    const float* Wk    = (const float*)d_in[14];
    const float* bk    = (const float*)d_in[15];
    const float* Wv    = (const float*)d_in[16];
    const float* bv    = (const float*)d_in[17];
    const float* w_val = (const float*)d_in[18];
    const float* b_val = (const float*)d_in[19];
    const float* dist  = (const float*)d_in[20];
    float* out = (float*)d_out;

    cudaFuncSetAttribute(k_final, cudaFuncAttributeMaxDynamicSharedMemorySize, WC_BYTES);

    k_init<<<1, 32>>>();
    k_prep_qkv<<<dim3(BB, 2), 384>>>(user, poi, tod, dow, lat, lon, ut, ue, pe, te, de,
                                     Wq, bq, Wk, bk, Wv, bv, dist);
    k_att<<<BB, 512>>>();
    k_final<<<dim3((PP + PT - 1)/PT, BB), NT, WC_BYTES>>>(pe, dist, poi, w_val, b_val, out, out_size);
}

// round 11
// speedup vs baseline: 2.3434x; 1.0920x over previous
#include <cuda_runtime.h>
#include <cstdint>

#define BB 64
#define LL 25
#define FF 128
#define PP 10000
#define PT 256        // p-tile per block (2 per thread)
#define NT 128        // threads per k_final block
#define KC 16         // f per W chunk
#define NCH (FF/KC)   // 8 chunks
#define WROW 20       // padded row stride (words) for W chunk (conflict-free)
#define WC_BYTES (2*PT*WROW*4)   // 40960
#define AST 28        // padded l-stride of transposed attn

// ---------------- device scratch ----------------
__device__ float g_q[BB*LL*FF];
__device__ float g_k[BB*LL*FF];
__device__ float g_v[BB*LL*FF];
__device__ float g_attnT[BB*FF*AST];   // transposed attn: [b][f][l(padded 28)]
__device__ float g_ds[BB*LL*LL];
__device__ float g_dt[BB*LL*LL];
__device__ float g_tint[BB*LL];
// 0:ds max 1:ds min 2:dt max 3:dt min 4:is max 5:is min 6:ti max 7:ti min
__device__ int g_stats[8];

__device__ __forceinline__ void redMax(float v, int slot) {
    #pragma unroll
    for (int o = 16; o; o >>= 1) v = fmaxf(v, __shfl_xor_sync(0xffffffffu, v, o));
    if ((threadIdx.x & 31) == 0) atomicMax(&g_stats[slot], __float_as_int(v));
}
__device__ __forceinline__ void redMin(float v, int slot) {
    #pragma unroll
    for (int o = 16; o; o >>= 1) v = fminf(v, __shfl_xor_sync(0xffffffffu, v, o));
    if ((threadIdx.x & 31) == 0) atomicMin(&g_stats[slot], __float_as_int(v));
}

// packed fp32x2 FMA (Blackwell FFMA2, only reachable via PTX)
__device__ __forceinline__ void ffma2(unsigned long long& d, unsigned long long a, unsigned long long b) {
    asm("fma.rn.f32x2 %0, %1, %2, %0;" : "+l"(d) : "l"(a), "l"(b));
}
__device__ __forceinline__ unsigned long long pack2(float x, float y) {
    unsigned long long r; asm("mov.b64 %0, {%1, %2};" : "=l"(r) : "f"(x), "f"(y)); return r;
}
__device__ __forceinline__ float lo2(unsigned long long v) { return __uint_as_float((unsigned)v); }
__device__ __forceinline__ float hi2(unsigned long long v) { return __uint_as_float((unsigned)(v >> 32)); }

// async 16B copy global -> shared (LDGSTS)
__device__ __forceinline__ void cp16(unsigned dst_smem, const void* src) {
    asm volatile("cp.async.cg.shared.global [%0], [%1], 16;\n" :: "r"(dst_smem), "l"(src));
}
__device__ __forceinline__ void cp_commit() {
    asm volatile("cp.async.commit_group;\n");
}
template<int N> __device__ __forceinline__ void cp_wait() {
    asm volatile("cp.async.wait_group %0;\n" :: "n"(N));
}

// ---------------- kernel 0: init reduction slots -------------------------------
__global__ void k_init() {
    int t = threadIdx.x;
    if (t < 8) g_stats[t] = (t & 1) ? 0x7F800000 : 0;
}

// ---------------- kernel 1: embeddings + ds/dt + tint + QKV | dist scan --------
__global__ __launch_bounds__(384) void k_prep_qkv(
        const int* __restrict__ user, const int* __restrict__ poi,
        const int* __restrict__ tod, const int* __restrict__ dow,
        const float* __restrict__ lat, const float* __restrict__ lon,
        const float* __restrict__ ut,
        const float* __restrict__ ue, const float* __restrict__ pe,
        const float* __restrict__ te, const float* __restrict__ de,
        const float* __restrict__ Wq, const float* __restrict__ bq,
        const float* __restrict__ Wk, const float* __restrict__ bk,
        const float* __restrict__ Wv, const float* __restrict__ bv,
        const float* __restrict__ dist) {
    int b = blockIdx.x, tid = threadIdx.x;
    const float INF = __int_as_float(0x7F800000);

    if (blockIdx.y == 1) {
        float mx = 0.f, mn = INF;
        for (int idx = tid; idx < LL*(PP/4); idx += 384) {
            int l = idx / (PP/4), c = idx % (PP/4);
            const float4* d4 = (const float4*)(dist + (size_t)poi[b*LL + l] * PP);
            float4 v = d4[c];
            mx = fmaxf(mx, fmaxf(fmaxf(v.x, v.y), fmaxf(v.z, v.w)));
            mn = fminf(mn, fminf(fminf(v.x, v.y), fminf(v.z, v.w)));
        }
        redMax(mx, 4); redMin(mn, 5);
        return;
    }

    __shared__ __align__(16) float inT[FF*28];

    for (int o = tid; o < LL*FF; o += 384) {
        int l = o >> 7, f = o & 127;
        int base = b*LL + l;
        float v = ue[(size_t)user[base]*FF + f] + pe[(size_t)poi[base]*FF + f]
                + te[tod[base]*FF + f] + de[dow[base]*FF + f];
        inT[f*28 + l] = v;
    }
    for (int o = tid; o < FF*3; o += 384) inT[(o/3)*28 + 25 + (o%3)] = 0.f;

    const float rad = 0.017453292519943295f;
    float mxs = 0.f, mns = INF, mxt = 0.f, mnt = INF;
    for (int e = tid; e < LL*LL; e += 384) {
        int i = e / LL, j = e % LL;
        float la1 = lat[b*LL+i], lo1 = lon[b*LL+i];
        float la2 = lat[b*LL+j], lo2 = lon[b*LL+j];
        float a = 0.5f - 0.5f*cosf((la2-la1)*rad)
                + cosf(la1*rad)*cosf(la2*rad)*(1.0f - cosf((lo2-lo1)*rad))*0.5f;
        float ds = 12742.0f * asinf(sqrtf(a));
        float dt = fabsf(ut[b*LL+i] - ut[b*LL+j]);
        g_ds[b*LL*LL + e] = ds;
        g_dt[b*LL*LL + e] = dt;
        mxs = fmaxf(mxs, ds); mns = fminf(mns, ds);
        mxt = fmaxf(mxt, dt); mnt = fminf(mnt, dt);
    }
    float mxi = 0.f, mni = INF;
    if (tid < LL) {
        float ti = (tid == 0) ? 0.f : fabsf(ut[b*LL+tid] - ut[b*LL+tid-1]);
        g_tint[b*LL + tid] = ti;
        mxi = ti; mni = ti;
    }
    redMax(mxs, 0); redMin(mns, 1);
    redMax(mxt, 2); redMin(mnt, 3);
    redMax(mxi, 6); redMin(mni, 7);
    __syncthreads();

    {
        int m = tid >> 7, f = tid & 127;
        const float* W  = (m == 0) ? Wq : (m == 1) ? Wk : Wv;
        const float* bp = (m == 0) ? bq : (m == 1) ? bk : bv;
        float bias = bp[f];
        unsigned long long acc[13];
        unsigned long long binit = pack2(bias, bias);
        #pragma unroll
        for (int j = 0; j < 13; ++j) acc[j] = binit;

        #pragma unroll 4
        for (int g = 0; g < FF; ++g) {
            float w = W[g*FF + f];
            unsigned long long w2 = pack2(w, w);
            const ulonglong2* row = (const ulonglong2*)(inT + g*28);
            #pragma unroll
            for (int j = 0; j < 6; ++j) {
                ulonglong2 a = row[j];
                ffma2(acc[2*j],   a.x, w2);
                ffma2(acc[2*j+1], a.y, w2);
            }
            unsigned long long a6 = ((const unsigned long long*)(inT + g*28))[12];
            ffma2(acc[12], a6, w2);
        }
        float* dst = ((m == 0) ? g_q : (m == 1) ? g_k : g_v) + (size_t)b*LL*FF;
        #pragma unroll
        for (int j = 0; j < 12; ++j) {
            dst[(2*j)*FF + f]   = lo2(acc[j]);
            dst[(2*j+1)*FF + f] = hi2(acc[j]);
        }
        dst[24*FF + f] = lo2(acc[12]);
    }
}

// ---------------- kernel 2: per-batch attention (emits TRANSPOSED attn) --------
__global__ __launch_bounds__(512) void k_att() {
    int b = blockIdx.x, tid = threadIdx.x;
    __shared__ float qs[LL*FF], ks[LL*FF], vs[LL*FF], aw[LL*LL];
    for (int o = tid; o < LL*(FF/4); o += 512) {
        ((float4*)qs)[o] = ((const float4*)g_q)[(size_t)b*LL*(FF/4) + o];
        ((float4*)ks)[o] = ((const float4*)g_k)[(size_t)b*LL*(FF/4) + o];
        ((float4*)vs)[o] = ((const float4*)g_v)[(size_t)b*LL*(FF/4) + o];
    }
    __syncthreads();
    float su = __int_as_float(g_stats[0]), sl = __int_as_float(g_stats[1]);
    float tu = __int_as_float(g_stats[2]), tl = __int_as_float(g_stats[3]);
    float nis = -1.0f/(su - sl), nit = -1.0f/(tu - tl);
    for (int e = tid; e < LL*LL; e += 512) {
        int i = e / LL, j = e % LL;
        const float4* q4 = (const float4*)(qs + i*FF);
        const float4* k4 = (const float4*)(ks + j*FF);
        float s = 0.f;
        #pragma unroll
        for (int f = 0; f < FF/4; ++f) {
            float4 a = q4[f], c = k4[f];
            s += a.x*c.x + a.y*c.y + a.z*c.z + a.w*c.w;
        }
        float delta = 0.5f*(__expf(g_ds[b*LL*LL + e]*nis) + __expf(g_dt[b*LL*LL + e]*nit));
        aw[e] = s + delta;
    }
    __syncthreads();
    {
        int w = tid >> 5, lane = tid & 31;
        for (int row = w; row < LL; row += 16) {
            float v = (lane < LL) ? aw[row*LL + lane] : -1e30f;
            float m = v;
            #pragma unroll
            for (int o = 16; o; o >>= 1) m = fmaxf(m, __shfl_xor_sync(0xffffffffu, m, o));
            float e = (lane < LL) ? __expf(v - m) : 0.f;
            float s = e;
            #pragma unroll
            for (int o = 16; o; o >>= 1) s += __shfl_xor_sync(0xffffffffu, s, o);
            if (lane < LL) aw[row*LL + lane] = e / s;
        }
    }
    __syncthreads();
    // AV -> transposed output g_attnT[b][f][l], pads zeroed
    float* dstT = g_attnT + (size_t)b*FF*AST;
    for (int o = tid; o < LL*FF; o += 512) {
        int i = o >> 7, f = o & 127;
        float s = 0.f;
        #pragma unroll
        for (int j = 0; j < LL; ++j) s += aw[i*LL + j] * vs[j*FF + f];
        dstT[f*AST + i] = s;
    }
    for (int o = tid; o < FF*3; o += 512) dstT[(o/3)*AST + 25 + (o%3)] = 0.f;
}

// ---------------- kernel 3: fused candidate scoring ----------------------------
// acc pairs over l (transposed A): 13 f32x2 accs per p, TP=2 -> 52 acc regs.
__global__ __launch_bounds__(NT, 4) void k_final(
        const float* __restrict__ poi_emb, const float* __restrict__ dist,
        const int* __restrict__ poi, const float* __restrict__ w_val,
        const float* __restrict__ b_val, float* __restrict__ out, int out_size) {
    extern __shared__ __align__(16) float Wc[];           // 2 bufs x PT x WROW
    __shared__ __align__(16) float As[FF*AST];            // transposed attn 14.3KB
    __shared__ float sa_s[LL], se_s[LL];
    __shared__ unsigned drow_s[LL];

    int tid = threadIdx.x;
    int b = blockIdx.y;
    int p0 = blockIdx.x * PT;

    for (int o = tid; o < FF*AST/4; o += NT)
        ((float4*)As)[o] = ((const float4*)(g_attnT + (size_t)b*FF*AST))[o];
    if (tid < LL) {
        drow_s[tid] = (unsigned)poi[b*LL + tid];
        float Dt = __int_as_float(g_stats[6]) - __int_as_float(g_stats[7]);
        float s = 0.5f * w_val[tid];
        sa_s[tid] = s;
        se_s[tid] = s * __expf(-g_tint[b*LL + tid] / Dt);
    }

    unsigned wc_base = (unsigned)__cvta_generic_to_shared(Wc);
    auto issue = [&](int ch, int buf) {
        #pragma unroll
        for (int k = 0; k < 8; ++k) {
            int s = k*NT + tid;                          // 0..1023
            int row = s >> 2, seg = s & 3;               // row 0..255
            int prow = min(p0 + row, PP-1);
            const float* src = poi_emb + (size_t)prow*FF + ch*KC + seg*4;
            unsigned dst = wc_base + ((buf*PT + row)*WROW + seg*4)*4;
            cp16(dst, src);
        }
        cp_commit();
    };

    issue(0, 0);

    unsigned long long acc0[13], acc1[13];
    #pragma unroll
    for (int j = 0; j < 13; ++j) { acc0[j] = 0ull; acc1[j] = 0ull; }

    for (int ch = 0; ch < NCH; ++ch) {
        int buf = ch & 1;
        if (ch + 1 < NCH) issue(ch + 1, (ch + 1) & 1);
        if (ch + 1 < NCH) cp_wait<1>(); else cp_wait<0>();
        __syncthreads();

        const float* w0 = Wc + (buf*PT + tid)*WROW;
        const float* w1 = Wc + (buf*PT + tid + NT)*WROW;
        #pragma unroll
        for (int fg = 0; fg < KC/4; ++fg) {
            float4 wa4 = ((const float4*)w0)[fg];
            float4 wb4 = ((const float4*)w1)[fg];
            #pragma unroll
            for (int ff = 0; ff < 4; ++ff) {
                int f = ch*KC + fg*4 + ff;
                float wa = (ff==0)?wa4.x:(ff==1)?wa4.y:(ff==2)?wa4.z:wa4.w;
                float wb = (ff==0)?wb4.x:(ff==1)?wb4.y:(ff==2)?wb4.z:wb4.w;
                unsigned long long wa2 = pack2(wa, wa);
                unsigned long long wb2 = pack2(wb, wb);
                const ulonglong2* arow = (const ulonglong2*)(As + f*AST);  // broadcast
                #pragma unroll
                for (int j = 0; j < 6; ++j) {
                    ulonglong2 a = arow[j];              // l = 4j..4j+3
                    ffma2(acc0[2*j],   a.x, wa2);
                    ffma2(acc0[2*j+1], a.y, wa2);
                    ffma2(acc1[2*j],   a.x, wb2);
                    ffma2(acc1[2*j+1], a.y, wb2);
                }
                unsigned long long a12 = ((const unsigned long long*)(As + f*AST))[12]; // l=24,25
                ffma2(acc0[12], a12, wa2);
                ffma2(acc1[12], a12, wb2);
            }
        }
        __syncthreads();
    }

    // epilogue
    int pA = p0 + tid, pB = p0 + tid + NT;
    int pcA = min(pA, PP-1), pcB = min(pB, PP-1);
    float nis = -1.0f / (__int_as_float(g_stats[4]) - __int_as_float(g_stats[5]));
    float bvv = b_val[0];
    bool dup = (out_size >= 2*BB*PP);

    float preA = bvv, preB = bvv;
    #pragma unroll
    for (int l = 0; l < LL; ++l) {
        const float* drow = dist + (size_t)drow_s[l]*PP;
        float dA = drow[pcA];
        float dB = drow[pcB];
        float sa = sa_s[l], se = se_s[l];
        float g0 = (l & 1) ? hi2(acc0[l>>1]) : lo2(acc0[l>>1]);
        float g1 = (l & 1) ? hi2(acc1[l>>1]) : lo2(acc1[l>>1]);
        preA += (sa * __expf(dA*nis) + se) * g0;
        preB += (sa * __expf(dB*nis) + se) * g1;
    }
    if (pA < PP) {
        int n = b*PP + pA;
        out[n] = preA;
        if (dup) out[BB*PP + n] = preA;
    }
    if (pB < PP) {
        int n = b*PP + pB;
        out[n] = preB;
        if (dup) out[BB*PP + n] = preB;
    }
}

// ---------------- launch ------------------------------------------------------
extern "C" void kernel_launch(void* const* d_in, const int* in_sizes, int n_in,
                              void* d_out, int out_size) {
    const int*   user  = (const int*)d_in[0];
    const int*   poi   = (const int*)d_in[1];
    // d_in[2] = cat (unused)
    const float* lat   = (const float*)d_in[3];
    const float* lon   = (const float*)d_in[4];
    const int*   tod   = (const int*)d_in[5];
    const int*   dow   = (const int*)d_in[6];
    const float* ut    = (const float*)d_in[7];
    const float* ue    = (const float*)d_in[8];
    const float* pe    = (const float*)d_in[9];
    const float* te    = (const float*)d_in[10];
    const float* de    = (const float*)d_in[11];
    const float* Wq    = (const float*)d_in[12];
    const float* bq    = (const float*)d_in[13];
    const float* Wk    = (const float*)d_in[14];
    const float* bk    = (const float*)d_in[15];
    const float* Wv    = (const float*)d_in[16];
    const float* bv    = (const float*)d_in[17];
    const float* w_val = (const float*)d_in[18];
    const float* b_val = (const float*)d_in[19];
    const float* dist  = (const float*)d_in[20];
    float* out = (float*)d_out;

    cudaFuncSetAttribute(k_final, cudaFuncAttributeMaxDynamicSharedMemorySize, WC_BYTES);

    k_init<<<1, 32>>>();
    k_prep_qkv<<<dim3(BB, 2), 384>>>(user, poi, tod, dow, lat, lon, ut, ue, pe, te, de,
                                     Wq, bq, Wk, bk, Wv, bv, dist);
    k_att<<<BB, 512>>>();
    k_final<<<dim3((PP + PT - 1)/PT, BB), NT, WC_BYTES>>>(pe, dist, poi, w_val, b_val, out, out_size);
}